// round 7
// baseline (speedup 1.0000x reference)
#include <cuda_runtime.h>
#include <cuda_fp16.h>
#include <cstdint>

// ============================================================================
// Persistent-CTA design: all of B (fp16 W_eff^T) resident in smem, A straight
// from global (LDG.64 -> cvt -> mma), zero mainloop barriers, work stealing.
// ============================================================================
#define KDIM     784
#define KPAD     800
#define NITER    49             // KDIM / 16
#define NGRID    148            // 1 CTA per SM (persistent)
#define THREADS  512            // 16 warps, warp tile M16 x N128
#define UNIT_M   256            // rows per stolen work unit (16 warps x 16)

#define BPITCHH  792            // halves per B row in smem (conflict-free)
#define BPITCHB  (BPITCHH * 2)  // 1584 bytes
#define B_BYTES  (128 * BPITCHB)        // 202752
#define OFW2     B_BYTES                 // 1280 floats
#define OFB1     (OFW2 + 5120)           // 128 floats
#define OFB2     (OFB1 + 512)            // 10 floats (+pad)
#define OFT      (OFB2 + 64)             // broadcast slot
#define SMEM_TOTAL (OFT + 16)            // 208480 B  (< 227 KB opt-in)

// W_eff transposed, fp16-RN: g_Wt16[n*KPAD + k] = fp16(W_eff[k][n])
__device__ __align__(16) __half g_Wt16[128 * KPAD];
__device__ unsigned g_ctr;               // work-stealing counter (reset by prep)

// ============================================================================
// helpers (baseline PTX only — no 'a'-suffix features survive compute_103)
// ============================================================================
__device__ __forceinline__ uint32_t smem_u32(const void* p) {
    uint32_t a;
    asm("{ .reg .u64 t; cvta.to.shared.u64 t, %1; cvt.u32.u64 %0, t; }" : "=r"(a) : "l"(p));
    return a;
}
__device__ __forceinline__ uint32_t pack_f16x2(float lo, float hi) {
    uint32_t r;
    asm("cvt.rn.f16x2.f32 %0, %2, %1;" : "=r"(r) : "f"(lo), "f"(hi));
    return r;
}
__device__ __forceinline__ void cp_async16(uint32_t dst_smem, const void* src) {
    asm volatile("cp.async.cg.shared.global [%0], [%1], 16;" :: "r"(dst_smem), "l"(src) : "memory");
}
__device__ __forceinline__ void cp_commit() { asm volatile("cp.async.commit_group;" ::: "memory"); }
__device__ __forceinline__ void cp_wait0()  { asm volatile("cp.async.wait_group 0;" ::: "memory"); }

__device__ __forceinline__ void ldmatrix_x4(uint32_t* r, uint32_t addr) {
    asm volatile("ldmatrix.sync.aligned.m8n8.x4.shared.b16 {%0,%1,%2,%3}, [%4];"
                 : "=r"(r[0]), "=r"(r[1]), "=r"(r[2]), "=r"(r[3]) : "r"(addr));
}
__device__ __forceinline__ void mma_f16(float* c, const uint32_t* a, uint32_t b0, uint32_t b1) {
    asm volatile("mma.sync.aligned.m16n8k16.row.col.f32.f16.f16.f32 "
                 "{%0,%1,%2,%3}, {%4,%5,%6,%7}, {%8,%9}, {%0,%1,%2,%3};"
                 : "+f"(c[0]), "+f"(c[1]), "+f"(c[2]), "+f"(c[3])
                 : "r"(a[0]), "r"(a[1]), "r"(a[2]), "r"(a[3]), "r"(b0), "r"(b1));
}

// ============================================================================
// Prep kernel: W_eff^T = (conv ⊗ w1), fp16-RN; also resets the work counter
// ============================================================================
__global__ void prep_kernel(const float* __restrict__ conv_w, const float* __restrict__ w1) {
    int idx = blockIdx.x * blockDim.x + threadIdx.x;
    if (idx == 0) g_ctr = 0u;
    if (idx >= 128 * KPAD) return;
    int n = idx / KPAD;
    int k = idx - n * KPAD;
    float v = 0.f;
    if (k < KDIM) {
        int i = k / 28, j = k - (k / 28) * 28;
        #pragma unroll
        for (int dy = 0; dy < 3; ++dy) {
            int r = i - dy;
            if (r < 0 || r >= 26) continue;
            #pragma unroll
            for (int dx = 0; dx < 3; ++dx) {
                int c = j - dx;
                if (c < 0 || c >= 26) continue;
                v += conv_w[dy * 3 + dx] * w1[(r * 26 + c) * 128 + n];
            }
        }
    }
    g_Wt16[idx] = __float2half_rn(v);
}

// ============================================================================
// Main persistent kernel: out = relu(x @ W_eff + b1) @ w2 + b2
// ============================================================================
__global__ void __launch_bounds__(THREADS, 1)
fused_mlp_kernel(const float* __restrict__ x, const float* __restrict__ b1,
                 const float* __restrict__ w2, const float* __restrict__ b2,
                 float* __restrict__ out, int Brows, int nunits) {
    extern __shared__ char smc[];
    float* w2s = (float*)(smc + OFW2);
    float* b1s = (float*)(smc + OFB1);
    float* b2s = (float*)(smc + OFB2);
    volatile int* tsh = (volatile int*)(smc + OFT);

    const int tid  = threadIdx.x;
    const int w    = tid >> 5;
    const int lane = tid & 31;
    const int tg   = lane >> 2;
    const int tk   = lane & 3;
    const uint32_t smb = smem_u32(smc);

    // constants
    for (int i = tid; i < 1280; i += THREADS) w2s[i] = w2[i];
    if (tid < 128) b1s[tid] = b1[tid];
    if (tid < 10)  b2s[tid] = b2[tid];

    // ---- one-time B load: 128 rows x 98 x 16B pieces ----
    for (int c = tid; c < 128 * 98; c += THREADS) {
        const int row = c / 98, p = c - row * 98;
        cp_async16(smb + (uint32_t)(row * BPITCHB + p * 16), g_Wt16 + (size_t)row * KPAD + p * 8);
    }
    cp_commit(); cp_wait0();
    __syncthreads();

    // per-lane ldmatrix base: lanes 0-7 rows r..r+7 @klo, 8-15 same rows @k+8,
    // 16-23 rows +8 @klo, 24-31 rows +8 @k+8   (within a 16-row n-group)
    const uint32_t lmb = smb + (uint32_t)(((lane & 7) + ((lane & 16) >> 1)) * BPITCHB)
                             + (uint32_t)((lane & 8) ? 16 : 0);

    // ---- persistent work loop ----
    while (true) {
        if (tid == 0) *tsh = (int)atomicAdd(&g_ctr, 1u);
        __syncthreads();
        const int t = *tsh;
        __syncthreads();
        if (t >= nunits) break;

        const int m0  = t * UNIT_M;
        const int rlo = m0 + 16 * w + tg;       // this lane's low row
        const int rhi = rlo + 8;
        const int clo = (rlo < Brows) ? rlo : (Brows - 1);
        const int chi = (rhi < Brows) ? rhi : (Brows - 1);
        const float* xlo = x + (size_t)clo * KDIM + 2 * tk;
        const float* xhi = x + (size_t)chi * KDIM + 2 * tk;

        float acc[16][4];
        #pragma unroll
        for (int ni = 0; ni < 16; ++ni)
            #pragma unroll
            for (int e = 0; e < 4; ++e) acc[ni][e] = 0.f;

        // A double-buffer prefetch (2 iterations deep)
        float2 pA[4], pB[4];
        pA[0] = *(const float2*)(xlo);      pA[1] = *(const float2*)(xhi);
        pA[2] = *(const float2*)(xlo + 8);  pA[3] = *(const float2*)(xhi + 8);
        pB[0] = *(const float2*)(xlo + 16); pB[1] = *(const float2*)(xhi + 16);
        pB[2] = *(const float2*)(xlo + 24); pB[3] = *(const float2*)(xhi + 24);

        #define BODY(IT, BUF, KP)                                                       \
        {                                                                               \
            uint32_t a[4];                                                              \
            a[0] = pack_f16x2(BUF[0].x, BUF[0].y);                                      \
            a[1] = pack_f16x2(BUF[1].x, BUF[1].y);                                      \
            a[2] = pack_f16x2(BUF[2].x, BUF[2].y);                                      \
            a[3] = pack_f16x2(BUF[3].x, BUF[3].y);                                      \
            if ((KP) < KDIM) {                                                          \
                BUF[0] = *(const float2*)(xlo + (KP));                                  \
                BUF[1] = *(const float2*)(xhi + (KP));                                  \
                BUF[2] = *(const float2*)(xlo + (KP) + 8);                              \
                BUF[3] = *(const float2*)(xhi + (KP) + 8);                              \
            }                                                                           \
            const uint32_t kb = lmb + (uint32_t)((IT) * 32);                            \
            _Pragma("unroll")                                                           \
            for (int p = 0; p < 8; ++p) {                                               \
                uint32_t r[4];                                                          \
                ldmatrix_x4(r, kb + (uint32_t)(p * 16 * BPITCHB));                      \
                mma_f16(acc[2 * p],     a, r[0], r[1]);                                 \
                mma_f16(acc[2 * p + 1], a, r[2], r[3]);                                 \
            }                                                                           \
        }

        #pragma unroll 2
        for (int it = 0; it < 48; it += 2) {
            BODY(it,     pA, (it + 2) * 16);
            BODY(it + 1, pB, (it + 3) * 16);
        }
        BODY(48, pA, KDIM);   // final iter, no prefetch
        #undef BODY

        // ---- per-warp epilogue: relu(+b1), tiny GEMM2, quad shfl-reduce, store ----
        float o_lo[10], o_hi[10];
        #pragma unroll
        for (int j = 0; j < 10; ++j) { o_lo[j] = 0.f; o_hi[j] = 0.f; }
        #pragma unroll
        for (int ni = 0; ni < 16; ++ni) {
            const int n0 = 8 * ni + 2 * tk;
            const float bn0 = b1s[n0], bn1 = b1s[n0 + 1];
            const float t0 = fmaxf(acc[ni][0] + bn0, 0.f);
            const float t1 = fmaxf(acc[ni][1] + bn1, 0.f);
            const float t2 = fmaxf(acc[ni][2] + bn0, 0.f);
            const float t3 = fmaxf(acc[ni][3] + bn1, 0.f);
            const float* w0 = w2s + n0 * 10;
            #pragma unroll
            for (int j = 0; j < 10; ++j) {
                o_lo[j] = fmaf(t0, w0[j], fmaf(t1, w0[10 + j], o_lo[j]));
                o_hi[j] = fmaf(t2, w0[j], fmaf(t3, w0[10 + j], o_hi[j]));
            }
        }
        #pragma unroll
        for (int j = 0; j < 10; ++j) {
            o_lo[j] += __shfl_xor_sync(0xFFFFFFFF, o_lo[j], 1);
            o_lo[j] += __shfl_xor_sync(0xFFFFFFFF, o_lo[j], 2);
            o_hi[j] += __shfl_xor_sync(0xFFFFFFFF, o_hi[j], 1);
            o_hi[j] += __shfl_xor_sync(0xFFFFFFFF, o_hi[j], 2);
        }
        if (tk == 0 && rlo < Brows) {
            float* dst = out + (size_t)rlo * 10;
            #pragma unroll
            for (int j = 0; j < 10; ++j) dst[j] = o_lo[j] + b2s[j];
        }
        if (tk == 1 && rhi < Brows) {
            float* dst = out + (size_t)rhi * 10;
            #pragma unroll
            for (int j = 0; j < 10; ++j) dst[j] = o_hi[j] + b2s[j];
        }
    }
}

// ============================================================================
// Host launch
// ============================================================================
extern "C" void kernel_launch(void* const* d_in, const int* in_sizes, int n_in,
                              void* d_out, int out_size) {
    const float* x      = (const float*)d_in[0];
    const float* conv_w = (const float*)d_in[1];
    const float* w1     = (const float*)d_in[2];
    const float* b1     = (const float*)d_in[3];
    const float* w2     = (const float*)d_in[4];
    const float* b2     = (const float*)d_in[5];
    float* out          = (float*)d_out;
    const int Brows     = in_sizes[0] / KDIM;
    const int nunits    = (Brows + UNIT_M - 1) / UNIT_M;

    static int configured = 0;
    if (!configured) {
        cudaFuncSetAttribute(fused_mlp_kernel, cudaFuncAttributeMaxDynamicSharedMemorySize, SMEM_TOTAL);
        configured = 1;
    }

    prep_kernel<<<(128 * KPAD + 255) / 256, 256>>>(conv_w, w1);
    fused_mlp_kernel<<<NGRID, THREADS, SMEM_TOTAL>>>(x, b1, w2, b2, out, Brows, nunits);
}

// round 9
// speedup vs baseline: 1.1294x; 1.1294x over previous
#include <cuda_runtime.h>
#include <cuda_fp16.h>
#include <cstdint>

// ============================================================================
// fp16 MMA, all-fp16 smem stages, 5-stage ring, TWO chunks per barrier,
// ldmatrix for both A and B fragments. K padded 784 -> 800 (25 chunks of 32).
// R9 fix vs R8: A and B use DIFFERENT ldmatrix lane mappings (A = R6-proven
// rows lane&15 / k-half lane>>4; B = rows (lane&7)+((lane&16)>>1) / k-half lane&8).
// ============================================================================
#define KDIM      784
#define KPAD      800
#define KCH       32
#define NCHUNK    25
#define MT        128
#define NT        128
#define NSTAGES   5
#define THREADS   256         // 8 warps: 4 in M x 2 in N, warp tile M32xN64

#define A_BYTES   (MT * 80)                // 10240
#define B_BYTES   (NT * 80)                // 10240
#define STAGE_BYTES (A_BYTES + B_BYTES)    // 20480
#define PH        130                      // h staging pitch (floats)

// smem float offsets
#define OF_PIPE   0                        // 5*20480 B = 102400 B (25600 floats)
#define OF_W2     25600                    // 1280
#define OF_B1     26880                    // 128
#define OF_B2     27008                    // 16 (10 used)
#define SMEM_FLOATS 27024
#define SMEM_BYTES  (SMEM_FLOATS * 4)      // 108096 -> 2 CTAs/SM
// epilogue overlays (pipeline dead): h[128][130] = 16640 floats
#define OF_PART   16640                    // 256*10
#define OF_OUTS   19200                    // 1280

// W_eff transposed, fp16-RN: g_Wt16[n*KPAD + k] = fp16(W_eff[k][n]), 0 for k>=784
__device__ __align__(16) __half g_Wt16[NT * KPAD];

// ============================================================================
// helpers (baseline PTX only — no 'a'-suffix features survive compute_103)
// ============================================================================
__device__ __forceinline__ uint32_t smem_u32(const void* p) {
    uint32_t a;
    asm("{ .reg .u64 t; cvta.to.shared.u64 t, %1; cvt.u32.u64 %0, t; }" : "=r"(a) : "l"(p));
    return a;
}
__device__ __forceinline__ uint32_t pack_f16x2(float lo, float hi) {
    uint32_t r;
    asm("cvt.rn.f16x2.f32 %0, %2, %1;" : "=r"(r) : "f"(lo), "f"(hi));
    return r;
}
__device__ __forceinline__ void cp_async16(uint32_t dst_smem, const void* src) {
    asm volatile("cp.async.cg.shared.global [%0], [%1], 16;" :: "r"(dst_smem), "l"(src) : "memory");
}
__device__ __forceinline__ void cp_commit() { asm volatile("cp.async.commit_group;" ::: "memory"); }
__device__ __forceinline__ void cp_wait1()  { asm volatile("cp.async.wait_group 1;" ::: "memory"); }
__device__ __forceinline__ void cp_wait0()  { asm volatile("cp.async.wait_group 0;" ::: "memory"); }

__device__ __forceinline__ void ldmatrix_x4(uint32_t* r, uint32_t addr) {
    asm volatile("ldmatrix.sync.aligned.m8n8.x4.shared.b16 {%0,%1,%2,%3}, [%4];"
                 : "=r"(r[0]), "=r"(r[1]), "=r"(r[2]), "=r"(r[3]) : "r"(addr));
}
__device__ __forceinline__ void mma_f16(float* c, const uint32_t* a, uint32_t b0, uint32_t b1) {
    asm volatile("mma.sync.aligned.m16n8k16.row.col.f32.f16.f16.f32 "
                 "{%0,%1,%2,%3}, {%4,%5,%6,%7}, {%8,%9}, {%0,%1,%2,%3};"
                 : "+f"(c[0]), "+f"(c[1]), "+f"(c[2]), "+f"(c[3])
                 : "r"(a[0]), "r"(a[1]), "r"(a[2]), "r"(a[3]), "r"(b0), "r"(b1));
}

// ============================================================================
// Prep kernel: W_eff^T = (conv ⊗ w1), fp16-RN
// ============================================================================
__global__ void prep_kernel(const float* __restrict__ conv_w, const float* __restrict__ w1) {
    int idx = blockIdx.x * blockDim.x + threadIdx.x;
    if (idx >= NT * KPAD) return;
    int n = idx / KPAD;
    int k = idx - n * KPAD;
    float v = 0.f;
    if (k < KDIM) {
        int i = k / 28, j = k - (k / 28) * 28;
        #pragma unroll
        for (int dy = 0; dy < 3; ++dy) {
            int r = i - dy;
            if (r < 0 || r >= 26) continue;
            #pragma unroll
            for (int dx = 0; dx < 3; ++dx) {
                int c = j - dx;
                if (c < 0 || c >= 26) continue;
                v += conv_w[dy * 3 + dx] * w1[(r * 26 + c) * 128 + n];
            }
        }
    }
    g_Wt16[idx] = __float2half_rn(v);
}

// ============================================================================
// Main fused kernel: out = relu(x @ W_eff + b1) @ w2 + b2
// ============================================================================
__global__ void __launch_bounds__(THREADS, 2)
fused_mlp_kernel(const float* __restrict__ x, const float* __restrict__ b1,
                 const float* __restrict__ w2, const float* __restrict__ b2,
                 float* __restrict__ out, int Brows) {
    extern __shared__ float sm[];
    const int tid  = threadIdx.x;
    const int wid  = tid >> 5;
    const int lane = tid & 31;
    const int tg   = lane >> 2;
    const int tk   = lane & 3;
    const int mw   = (wid >> 1) * 32;    // 4 warps in M
    const int nw   = (wid & 1) * 64;     // 2 warps in N
    const int m0   = blockIdx.x * MT;

    for (int i = tid; i < 1280; i += THREADS) sm[OF_W2 + i] = w2[i];
    if (tid < 128) sm[OF_B1 + tid] = b1[tid];
    if (tid < 10)  sm[OF_B2 + tid] = b2[tid];

    const uint32_t pipe_sm = smem_u32(sm + OF_PIPE);

    // ---- producer addressing (R6-proven) ----
    const int prow = tid >> 2, pq = tid & 3;
    int msrc = m0 + prow; if (msrc >= Brows) msrc = Brows - 1;
    const float* xsrc = x + (size_t)msrc * KDIM + pq * 8;        // + c*KCH
    const __half* wsrc = g_Wt16 + (size_t)prow * KPAD + pq * 8;  // + c*KCH
    const uint32_t a_sts = (uint32_t)(prow * 80 + pq * 16);
    const uint32_t b_dst = a_sts;

    float4 rAf[4];
    auto ldgA = [&](int c) {
        const int k0 = c * KCH + pq * 8;
        #pragma unroll
        for (int p = 0; p < 2; ++p) {
            const float* s = xsrc + c * KCH + (size_t)p * 64 * KDIM;
            if (k0 < KDIM) {
                rAf[2 * p]     = *(const float4*)(s);
                rAf[2 * p + 1] = *(const float4*)(s + 4);
            } else {
                rAf[2 * p]     = make_float4(0.f, 0.f, 0.f, 0.f);
                rAf[2 * p + 1] = make_float4(0.f, 0.f, 0.f, 0.f);
            }
        }
    };
    auto stsA = [&](int stage) {
        #pragma unroll
        for (int p = 0; p < 2; ++p) {
            uint4 v;
            v.x = pack_f16x2(rAf[2 * p].x,     rAf[2 * p].y);
            v.y = pack_f16x2(rAf[2 * p].z,     rAf[2 * p].w);
            v.z = pack_f16x2(rAf[2 * p + 1].x, rAf[2 * p + 1].y);
            v.w = pack_f16x2(rAf[2 * p + 1].z, rAf[2 * p + 1].w);
            *(uint4*)((char*)sm + (size_t)stage * STAGE_BYTES + a_sts + (size_t)p * 64 * 80) = v;
        }
    };
    auto issueB = [&](int c, int stage) {
        const uint32_t bb = pipe_sm + (uint32_t)stage * STAGE_BYTES + A_BYTES;
        #pragma unroll
        for (int p = 0; p < 2; ++p)
            cp_async16(bb + b_dst + (uint32_t)p * 64 * 80,
                       wsrc + c * KCH + (size_t)p * 64 * KPAD);
    };

    float acc[2][8][4];
    #pragma unroll
    for (int mi = 0; mi < 2; ++mi)
        #pragma unroll
        for (int ni = 0; ni < 8; ++ni)
            #pragma unroll
            for (int e = 0; e < 4; ++e) acc[mi][ni][e] = 0.f;

    // ---- ldmatrix lane mappings (DIFFERENT for A and B!) ----
    // A (m16 fragment order a0=rows0-15@k ... a2=rows0-15@k+8):
    //   lanes 0-15 -> rows mw+0..15 @k, lanes 16-31 -> same rows @k+8 (+16B)
    const uint32_t a_lm = (uint32_t)(mw + (lane & 15)) * 80 + (uint32_t)((lane >> 4) << 4);
    // B (pairs b0,b1 per 8-row n-group):
    //   lanes 0-7 -> rows n..n+7 @k, 8-15 -> same rows @k+8, 16-23 -> rows+8 @k, 24-31 -> rows+8 @k+8
    const uint32_t b_lm = (uint32_t)A_BYTES
                        + (uint32_t)(nw + (lane & 7) + ((lane & 16) >> 1)) * 80
                        + (uint32_t)((lane & 8) ? 16 : 0);

    // ---- consume one chunk ----
    auto consume = [&](int stage) {
        const uint32_t sb = pipe_sm + (uint32_t)stage * STAGE_BYTES;
        #pragma unroll
        for (int ks = 0; ks < KCH; ks += 16) {
            uint32_t a[2][4];
            #pragma unroll
            for (int mi = 0; mi < 2; ++mi)
                ldmatrix_x4(a[mi], sb + a_lm + (uint32_t)(mi * 16 * 80 + ks * 2));
            uint32_t b[8][2];
            #pragma unroll
            for (int g = 0; g < 4; ++g) {
                uint32_t r[4];
                ldmatrix_x4(r, sb + b_lm + (uint32_t)(g * 16 * 80 + ks * 2));
                b[2 * g][0]     = r[0]; b[2 * g][1]     = r[1];
                b[2 * g + 1][0] = r[2]; b[2 * g + 1][1] = r[3];
            }
            #pragma unroll
            for (int mi = 0; mi < 2; ++mi)
                #pragma unroll
                for (int ni = 0; ni < 8; ++ni)
                    mma_f16(acc[mi][ni], a[mi], b[ni][0], b[ni][1]);
        }
    };

    // ---- prologue: A chunks 0,1 staged; B chunks 0..2 in flight ----
    ldgA(0); stsA(0);
    ldgA(1); stsA(1);
    issueB(0, 0); cp_commit();
    issueB(1, 1); cp_commit();
    issueB(2, 2); cp_commit();

    // ---- mainloop: 2 chunks per barrier (13 rendezvous total) ----
    for (int p = 0; p < NCHUNK; p += 2) {
        cp_wait1();          // B(p), B(p+1) complete (only B(p+2) may remain pending)
        __syncthreads();     // stsA(p),stsA(p+1) visible; stages (p+3..p+4)%5 free

        if (p + 3 < NCHUNK) issueB(p + 3, (p + 3) % NSTAGES);
        cp_commit();
        if (p + 4 < NCHUNK) issueB(p + 4, (p + 4) % NSTAGES);
        cp_commit();

        if (p + 2 < NCHUNK) ldgA(p + 2);
        consume(p % NSTAGES);
        if (p + 2 < NCHUNK) stsA((p + 2) % NSTAGES);

        if (p + 3 < NCHUNK) ldgA(p + 3);
        if (p + 1 < NCHUNK) consume((p + 1) % NSTAGES);
        if (p + 3 < NCHUNK) stsA((p + 3) % NSTAGES);
    }

    // ---- epilogue: h = relu(acc + b1) into smem overlay ----
    cp_wait0();
    __syncthreads();
    {
        float* h = sm + OF_PIPE;   // [128][PH]
        #pragma unroll
        for (int mi = 0; mi < 2; ++mi) {
            #pragma unroll
            for (int ni = 0; ni < 8; ++ni) {
                const int r = mw + mi * 16 + tg;
                const int n = nw + ni * 8 + 2 * tk;
                const float bn0 = sm[OF_B1 + n], bn1 = sm[OF_B1 + n + 1];
                h[r * PH + n]           = fmaxf(acc[mi][ni][0] + bn0, 0.f);
                h[r * PH + n + 1]       = fmaxf(acc[mi][ni][1] + bn1, 0.f);
                h[(r + 8) * PH + n]     = fmaxf(acc[mi][ni][2] + bn0, 0.f);
                h[(r + 8) * PH + n + 1] = fmaxf(acc[mi][ni][3] + bn1, 0.f);
            }
        }
    }
    __syncthreads();

    // ---- GEMM2: split-K over 2 threads/row ----
    {
        const float* h = sm + OF_PIPE;
        const int row  = tid & 127;
        const int half = tid >> 7;
        float o[10];
        #pragma unroll
        for (int n = 0; n < 10; ++n) o[n] = 0.f;
        #pragma unroll 8
        for (int k = half * 64; k < half * 64 + 64; ++k) {
            const float t = h[row * PH + k];
            const float* wr = sm + OF_W2 + k * 10;
            #pragma unroll
            for (int n = 0; n < 10; ++n) o[n] = fmaf(t, wr[n], o[n]);
        }
        #pragma unroll
        for (int n = 0; n < 10; ++n) sm[OF_PART + tid * 10 + n] = o[n];
    }
    __syncthreads();
    if (tid < 128) {
        #pragma unroll
        for (int n = 0; n < 10; ++n)
            sm[OF_OUTS + tid * 10 + n] = sm[OF_PART + tid * 10 + n]
                                       + sm[OF_PART + (tid + 128) * 10 + n]
                                       + sm[OF_B2 + n];
    }
    __syncthreads();

    // ---- coalesced store ----
    const int nvalid = (Brows - m0 < MT) ? (Brows - m0) : MT;
    if (nvalid == MT) {
        float4* dst = (float4*)(out + (size_t)m0 * 10);
        const float4* src = (const float4*)(sm + OF_OUTS);
        for (int i = tid; i < MT * 10 / 4; i += THREADS) dst[i] = src[i];
    } else {
        for (int i = tid; i < nvalid * 10; i += THREADS) out[(size_t)m0 * 10 + i] = sm[OF_OUTS + i];
    }
}

// ============================================================================
// Host launch
// ============================================================================
extern "C" void kernel_launch(void* const* d_in, const int* in_sizes, int n_in,
                              void* d_out, int out_size) {
    const float* x      = (const float*)d_in[0];
    const float* conv_w = (const float*)d_in[1];
    const float* w1     = (const float*)d_in[2];
    const float* b1     = (const float*)d_in[3];
    const float* w2     = (const float*)d_in[4];
    const float* b2     = (const float*)d_in[5];
    float* out          = (float*)d_out;
    const int Brows     = in_sizes[0] / KDIM;

    static int configured = 0;
    if (!configured) {
        cudaFuncSetAttribute(fused_mlp_kernel, cudaFuncAttributeMaxDynamicSharedMemorySize, SMEM_BYTES);
        configured = 1;
    }

    prep_kernel<<<(NT * KPAD + 255) / 256, 256>>>(conv_w, w1);

    const int grid = (Brows + MT - 1) / MT;
    fused_mlp_kernel<<<grid, THREADS, SMEM_BYTES>>>(x, b1, w2, b2, out, Brows);
}

// round 10
// speedup vs baseline: 1.4473x; 1.2815x over previous
#include <cuda_runtime.h>
#include <cuda_fp16.h>
#include <cstdint>

// ============================================================================
// R10 = exact R4 structure (fastest so far) + B fragments via ldmatrix.x4
// fp16 MMA; A fp32 in smem (cp.async) -> LDS.64 + cvt; B fp16 in smem -> LDSM.
// K padded 784 -> 800 (25 chunks of 32).
// ============================================================================
#define KDIM      784
#define KPAD      800
#define KCH       32          // K per pipeline chunk
#define NCHUNK    25          // KPAD / KCH
#define MT        128
#define NT        128
#define NSTAGES   3
#define THREADS   256         // 8 warps: 4 in M x 2 in N, warp tile M32xN64

// A tile: fp32, pitch 40 floats (160 B). LDS.64 pattern conflict-free (R4-proven).
// B tile: fp16, pitch 40 halves (80 B). ldmatrix rows at 20k mod 32 words ->
// all 32 banks, conflict-free (R9-proven).
#define APITCH    40                        // floats
#define A_BYTES   (MT * APITCH * 4)         // 20480
#define B_BYTES   (NT * 80)                 // 10240
#define STAGE_BYTES (A_BYTES + B_BYTES)     // 30720
#define STAGE_F   (STAGE_BYTES / 4)         // 7680 floats
#define PH        130                       // h staging pitch (floats)

// smem float offsets
#define OF_PIPE   0                         // 3*7680 = 23040 floats (92160 B)
#define OF_W2     23040                     // 1280
#define OF_B1     24320                     // 128
#define OF_B2     24448                     // 16 (10 used)
#define SMEM_FLOATS 24464
#define SMEM_BYTES  (SMEM_FLOATS * 4)       // 97856 -> 2 CTAs/SM
// epilogue overlays (pipeline dead): h[128][130] = 16640 floats
#define OF_PART   16640                     // 256*10
#define OF_OUTS   19200                     // 1280

// W_eff transposed, fp16-RN: g_Wt16[n*KPAD + k] = fp16(W_eff[k][n]), 0 for k>=784
__device__ __align__(16) __half g_Wt16[NT * KPAD];

// ============================================================================
// helpers (baseline PTX only — no 'a'-suffix features survive compute_103)
// ============================================================================
__device__ __forceinline__ uint32_t smem_u32(const void* p) {
    uint32_t a;
    asm("{ .reg .u64 t; cvta.to.shared.u64 t, %1; cvt.u32.u64 %0, t; }" : "=r"(a) : "l"(p));
    return a;
}
__device__ __forceinline__ uint32_t pack_f16x2(float lo, float hi) {
    uint32_t r;
    asm("cvt.rn.f16x2.f32 %0, %2, %1;" : "=r"(r) : "f"(lo), "f"(hi));
    return r;
}
__device__ __forceinline__ void cp_async16(uint32_t dst_smem, const void* src) {
    asm volatile("cp.async.cg.shared.global [%0], [%1], 16;" :: "r"(dst_smem), "l"(src) : "memory");
}
__device__ __forceinline__ void cp_async16_pred(uint32_t dst_smem, const void* src, int src_bytes) {
    asm volatile("cp.async.cg.shared.global [%0], [%1], 16, %2;"
                 :: "r"(dst_smem), "l"(src), "r"(src_bytes) : "memory");
}
__device__ __forceinline__ void cp_commit() { asm volatile("cp.async.commit_group;" ::: "memory"); }
__device__ __forceinline__ void cp_wait1()  { asm volatile("cp.async.wait_group 1;" ::: "memory"); }
__device__ __forceinline__ void cp_wait0()  { asm volatile("cp.async.wait_group 0;" ::: "memory"); }

__device__ __forceinline__ void ldmatrix_x4(uint32_t* r, uint32_t addr) {
    asm volatile("ldmatrix.sync.aligned.m8n8.x4.shared.b16 {%0,%1,%2,%3}, [%4];"
                 : "=r"(r[0]), "=r"(r[1]), "=r"(r[2]), "=r"(r[3]) : "r"(addr));
}
__device__ __forceinline__ void mma_f16(float* c, const uint32_t* a, uint32_t b0, uint32_t b1) {
    asm volatile("mma.sync.aligned.m16n8k16.row.col.f32.f16.f16.f32 "
                 "{%0,%1,%2,%3}, {%4,%5,%6,%7}, {%8,%9}, {%0,%1,%2,%3};"
                 : "+f"(c[0]), "+f"(c[1]), "+f"(c[2]), "+f"(c[3])
                 : "r"(a[0]), "r"(a[1]), "r"(a[2]), "r"(a[3]), "r"(b0), "r"(b1));
}

// ============================================================================
// Prep kernel: W_eff^T = (conv ⊗ w1), fp16-RN
// ============================================================================
__global__ void prep_kernel(const float* __restrict__ conv_w, const float* __restrict__ w1) {
    int idx = blockIdx.x * blockDim.x + threadIdx.x;
    if (idx >= NT * KPAD) return;
    int n = idx / KPAD;
    int k = idx - n * KPAD;
    float v = 0.f;
    if (k < KDIM) {
        int i = k / 28, j = k - (k / 28) * 28;
        #pragma unroll
        for (int dy = 0; dy < 3; ++dy) {
            int r = i - dy;
            if (r < 0 || r >= 26) continue;
            #pragma unroll
            for (int dx = 0; dx < 3; ++dx) {
                int c = j - dx;
                if (c < 0 || c >= 26) continue;
                v += conv_w[dy * 3 + dx] * w1[(r * 26 + c) * 128 + n];
            }
        }
    }
    g_Wt16[idx] = __float2half_rn(v);
}

// ============================================================================
// Main fused kernel: out = relu(x @ W_eff + b1) @ w2 + b2
// ============================================================================
__global__ void __launch_bounds__(THREADS, 2)
fused_mlp_kernel(const float* __restrict__ x, const float* __restrict__ b1,
                 const float* __restrict__ w2, const float* __restrict__ b2,
                 float* __restrict__ out, int Brows) {
    extern __shared__ float sm[];
    const int tid  = threadIdx.x;
    const int wid  = tid >> 5;
    const int lane = tid & 31;
    const int tg   = lane >> 2;          // 0..7
    const int tk   = lane & 3;           // 0..3
    const int mw   = (wid >> 1) * 32;    // 4 warps in M
    const int nw   = (wid & 1) * 64;     // 2 warps in N
    const int m0   = blockIdx.x * MT;

    for (int i = tid; i < 1280; i += THREADS) sm[OF_W2 + i] = w2[i];
    if (tid < 128) sm[OF_B1 + tid] = b1[tid];
    if (tid < 10)  sm[OF_B2 + tid] = b2[tid];

    const uint32_t pipe_sm = smem_u32(sm + OF_PIPE);

    // ---- producer (R4-verbatim): A 4 x 16B pieces/thread (zero-fill past K=784), B 2 ----
    auto issue = [&](int c, int stage) {
        const uint32_t sbase = pipe_sm + (uint32_t)stage * STAGE_BYTES;
        #pragma unroll
        for (int r = 0; r < 4; ++r) {
            const int j   = tid + r * THREADS;       // 0..1023
            const int row = j >> 3, q = j & 7;       // row, 16B piece (4 floats)
            int msrc = m0 + row; if (msrc >= Brows) msrc = Brows - 1;
            const int k0 = c * KCH + q * 4;
            cp_async16_pred(sbase + (uint32_t)(row * APITCH + q * 4) * 4,
                            x + (size_t)msrc * KDIM + k0,
                            (k0 < KDIM) ? 16 : 0);
        }
        const uint32_t bbase = sbase + A_BYTES;
        #pragma unroll
        for (int r = 0; r < 2; ++r) {
            const int j   = tid + r * THREADS;       // 0..511
            const int row = j >> 2, q = j & 3;       // row, 16B piece (8 halves)
            cp_async16(bbase + (uint32_t)(row * 80 + q * 16),
                       g_Wt16 + (size_t)row * KPAD + c * KCH + q * 8);
        }
    };

    float acc[2][8][4];
    #pragma unroll
    for (int mi = 0; mi < 2; ++mi)
        #pragma unroll
        for (int ni = 0; ni < 8; ++ni)
            #pragma unroll
            for (int e = 0; e < 4; ++e) acc[mi][ni][e] = 0.f;

    // B ldmatrix lane mapping (R9-proven):
    // lanes 0-7 -> rows nw+0..7 @k, 8-15 -> same rows @k+8 (+16B),
    // 16-23 -> rows +8 @k, 24-31 -> rows +8 @k+8
    const uint32_t b_lm = (uint32_t)A_BYTES
                        + (uint32_t)(nw + (lane & 7) + ((lane & 16) >> 1)) * 80
                        + (uint32_t)((lane & 8) ? 16 : 0);

    // ---- prologue: fill 2 stages ----
    issue(0, 0); cp_commit();
    issue(1, 1); cp_commit();

    // ---- mainloop (R4-verbatim structure) ----
    int stage = 0;
    for (int c = 0; c < NCHUNK; ++c) {
        cp_wait1();
        __syncthreads();

        const int cn = c + NSTAGES - 1;
        int nstage = stage + 2; if (nstage >= NSTAGES) nstage -= NSTAGES;
        if (cn < NCHUNK) issue(cn, nstage);
        cp_commit();

        const float* As = sm + OF_PIPE + stage * STAGE_F;
        const uint32_t sb = pipe_sm + (uint32_t)stage * STAGE_BYTES;

        #pragma unroll
        for (int ks = 0; ks < KCH; ks += 16) {
            // A fragments: fp32 LDS.64 + cvt (R4-proven)
            uint32_t a[2][4];
            #pragma unroll
            for (int mi = 0; mi < 2; ++mi) {
                const float2* r0 = (const float2*)(As + (mw + mi * 16 + tg) * APITCH + ks);
                const float2* r1 = (const float2*)(As + (mw + mi * 16 + tg + 8) * APITCH + ks);
                float2 v0 = r0[tk], v1 = r1[tk], v2 = r0[tk + 4], v3 = r1[tk + 4];
                a[mi][0] = pack_f16x2(v0.x, v0.y);
                a[mi][1] = pack_f16x2(v1.x, v1.y);
                a[mi][2] = pack_f16x2(v2.x, v2.y);
                a[mi][3] = pack_f16x2(v3.x, v3.y);
            }
            // B fragments: ldmatrix.x4, 4 groups of 16 n-rows (R9-proven mapping)
            uint32_t b[8][2];
            #pragma unroll
            for (int g = 0; g < 4; ++g) {
                uint32_t r[4];
                ldmatrix_x4(r, sb + b_lm + (uint32_t)(g * 16 * 80 + ks * 2));
                b[2 * g][0]     = r[0]; b[2 * g][1]     = r[1];
                b[2 * g + 1][0] = r[2]; b[2 * g + 1][1] = r[3];
            }
            #pragma unroll
            for (int mi = 0; mi < 2; ++mi)
                #pragma unroll
                for (int ni = 0; ni < 8; ++ni)
                    mma_f16(acc[mi][ni], a[mi], b[ni][0], b[ni][1]);
        }
        ++stage; if (stage >= NSTAGES) stage = 0;
    }

    // ---- epilogue: h = relu(acc + b1) into smem overlay (R4-verbatim) ----
    cp_wait0();
    __syncthreads();
    {
        float* h = sm + OF_PIPE;   // [128][PH]
        #pragma unroll
        for (int mi = 0; mi < 2; ++mi) {
            #pragma unroll
            for (int ni = 0; ni < 8; ++ni) {
                const int r = mw + mi * 16 + tg;
                const int n = nw + ni * 8 + 2 * tk;
                const float bn0 = sm[OF_B1 + n], bn1 = sm[OF_B1 + n + 1];
                h[r * PH + n]           = fmaxf(acc[mi][ni][0] + bn0, 0.f);
                h[r * PH + n + 1]       = fmaxf(acc[mi][ni][1] + bn1, 0.f);
                h[(r + 8) * PH + n]     = fmaxf(acc[mi][ni][2] + bn0, 0.f);
                h[(r + 8) * PH + n + 1] = fmaxf(acc[mi][ni][3] + bn1, 0.f);
            }
        }
    }
    __syncthreads();

    // ---- GEMM2: split-K over 2 threads/row ----
    {
        const float* h = sm + OF_PIPE;
        const int row  = tid & 127;
        const int half = tid >> 7;
        float o[10];
        #pragma unroll
        for (int n = 0; n < 10; ++n) o[n] = 0.f;
        #pragma unroll 8
        for (int k = half * 64; k < half * 64 + 64; ++k) {
            const float t = h[row * PH + k];
            const float* wr = sm + OF_W2 + k * 10;
            #pragma unroll
            for (int n = 0; n < 10; ++n) o[n] = fmaf(t, wr[n], o[n]);
        }
        #pragma unroll
        for (int n = 0; n < 10; ++n) sm[OF_PART + tid * 10 + n] = o[n];
    }
    __syncthreads();
    if (tid < 128) {
        #pragma unroll
        for (int n = 0; n < 10; ++n)
            sm[OF_OUTS + tid * 10 + n] = sm[OF_PART + tid * 10 + n]
                                       + sm[OF_PART + (tid + 128) * 10 + n]
                                       + sm[OF_B2 + n];
    }
    __syncthreads();

    // ---- coalesced store ----
    const int nvalid = (Brows - m0 < MT) ? (Brows - m0) : MT;
    if (nvalid == MT) {
        float4* dst = (float4*)(out + (size_t)m0 * 10);
        const float4* src = (const float4*)(sm + OF_OUTS);
        for (int i = tid; i < MT * 10 / 4; i += THREADS) dst[i] = src[i];
    } else {
        for (int i = tid; i < nvalid * 10; i += THREADS) out[(size_t)m0 * 10 + i] = sm[OF_OUTS + i];
    }
}

// ============================================================================
// Host launch
// ============================================================================
extern "C" void kernel_launch(void* const* d_in, const int* in_sizes, int n_in,
                              void* d_out, int out_size) {
    const float* x      = (const float*)d_in[0];
    const float* conv_w = (const float*)d_in[1];
    const float* w1     = (const float*)d_in[2];
    const float* b1     = (const float*)d_in[3];
    const float* w2     = (const float*)d_in[4];
    const float* b2     = (const float*)d_in[5];
    float* out          = (float*)d_out;
    const int Brows     = in_sizes[0] / KDIM;

    static int configured = 0;
    if (!configured) {
        cudaFuncSetAttribute(fused_mlp_kernel, cudaFuncAttributeMaxDynamicSharedMemorySize, SMEM_BYTES);
        configured = 1;
    }

    prep_kernel<<<(NT * KPAD + 255) / 256, 256>>>(conv_w, w1);

    const int grid = (Brows + MT - 1) / MT;
    fused_mlp_kernel<<<grid, THREADS, SMEM_BYTES>>>(x, b1, w2, b2, out, Brows);
}